// round 5
// baseline (speedup 1.0000x reference)
#include <cuda_runtime.h>
#include <mma.h>
#include <math.h>

using namespace nvcuda;

#define BB  128
#define SS  256
#define II  512
#define HH  1024
#define OO  512
#define TT  128
#define G4H 4096
#define NSTEP (SS + TT)
#define NCTA_REC 128
#define GA 8704            // floats per packed 128x68 K-chunk tile

// ---------------- static device scratch ----------------
__device__ __align__(128) float g_Ppk[(size_t)SS * 128 * 4096];     // packed P (512MB)
__device__ __align__(128) float g_xpk[(size_t)256 * 8 * GA];        // packed x
__device__ __align__(128) float g_WihEpk[(size_t)32 * 8 * GA];
__device__ __align__(128) float g_WihDpk[(size_t)32 * 8 * GA];
__device__ __align__(128) float g_WpTpk[(size_t)8 * 8 * GA];
__device__ __align__(128) float g_Wprojpk[(size_t)4 * 16 * GA];
__device__ __align__(128) float g_Hallpk[(size_t)128 * 16 * GA];    // decoder h, packed for final GEMM
__device__ __align__(128) float g_WpkE[64 * 32 * 64 * 36];          // rec-packed weights (pad 36)
__device__ __align__(128) float g_WpkD[64 * 32 * 64 * 36];
__device__ __align__(128) float g_WpkF[64 * 32 * 64 * 36];
__device__ __align__(128) float g_hT[2 * 2 * 32 * 32 * 68];         // double-buffered transposed h
__device__ float g_benc[G4H];
__device__ float g_bdec[G4H];
__device__ float g_beff[G4H];
__device__ unsigned g_bar;

// ---------------- helpers ----------------
__device__ __forceinline__ float tf32t(float x) {
    unsigned u;
    asm("cvt.rna.tf32.f32 %0, %1;" : "=r"(u) : "f"(x));
    return __uint_as_float(u);
}
__device__ __forceinline__ void mbar_init(unsigned mbar, unsigned cnt) {
    asm volatile("mbarrier.init.shared.b64 [%0], %1;" :: "r"(mbar), "r"(cnt) : "memory");
}
__device__ __forceinline__ void mbar_expect(unsigned mbar, unsigned bytes) {
    asm volatile("mbarrier.arrive.expect_tx.shared.b64 _, [%0], %1;"
                 :: "r"(mbar), "r"(bytes) : "memory");
}
__device__ __forceinline__ void mbar_wait(unsigned mbar, unsigned parity) {
    unsigned done = 0;
    while (!done) {
        asm volatile(
            "{\n\t.reg .pred p;\n\t"
            "mbarrier.try_wait.parity.acquire.cta.shared::cta.b64 p, [%1], %2, 0x989680;\n\t"
            "selp.b32 %0, 1, 0, p;\n\t}"
            : "=r"(done) : "r"(mbar), "r"(parity) : "memory");
    }
}
__device__ __forceinline__ void bulk_g2s(unsigned dst, const void* src, unsigned bytes,
                                         unsigned mbar) {
    asm volatile(
        "cp.async.bulk.shared::cluster.global.mbarrier::complete_tx::bytes [%0], [%1], %2, [%3];"
        :: "r"(dst), "l"(src), "r"(bytes), "r"(mbar) : "memory");
}
__device__ __forceinline__ void fence_async() {
    asm volatile("fence.proxy.async.shared::cta;" ::: "memory");
}

// ---------------- grid barrier ----------------
__device__ __forceinline__ void gridbar(int& epoch) {
    epoch++;
    __threadfence();
    __syncthreads();
    if (threadIdx.x == 0) {
        atomicAdd(&g_bar, 1u);
        const unsigned tgt = (unsigned)NCTA_REC * (unsigned)epoch;
        volatile unsigned* p = &g_bar;
        while (*p < tgt) { }
    }
    __syncthreads();
}
__global__ void k_reset_bar() { g_bar = 0u; }

// ---------------- small kernels ----------------
__global__ void k_zero(float* p, int n) {
    int i = blockIdx.x * blockDim.x + threadIdx.x;
    if (i < n) p[i] = 0.f;
}
__global__ void k_vec_add(const float* __restrict__ a, const float* __restrict__ b,
                          float* __restrict__ o, int n) {
    int i = blockIdx.x * blockDim.x + threadIdx.x;
    if (i < n) o[i] = a[i] + b[i];
}
__global__ void k_beff(const float* __restrict__ Wih, const float* __restrict__ bproj,
                       const float* __restrict__ bdec, float* __restrict__ beff) {
    int n = blockIdx.x * blockDim.x + threadIdx.x;
    if (n < G4H) {
        float s = bdec[n];
        const float* wr = Wih + (size_t)n * OO;
        #pragma unroll 8
        for (int o = 0; o < OO; o++) s += wr[o] * bproj[o];
        beff[n] = s;
    }
}
// generic pack: src [M][K] row-major -> dst [mtile][kc][128][68], tf32-truncated
__global__ void k_pack(const float* __restrict__ src, float* __restrict__ dst,
                       int K, size_t total) {
    size_t i = ((size_t)blockIdx.x * 256 + threadIdx.x) * 4;
    if (i < total) {
        int r = (int)(i / (unsigned)K);
        int k = (int)(i - (size_t)r * K);
        float4 v = *(const float4*)&src[i];
        v.x = tf32t(v.x); v.y = tf32t(v.y); v.z = tf32t(v.z); v.w = tf32t(v.w);
        int nk = K >> 6;
        size_t d = ((size_t)(r >> 7) * nk + (k >> 6)) * GA + (r & 127) * 68 + (k & 63);
        *(float4*)&dst[d] = v;
    }
}
// pack transpose of Wproj [O=512][H=1024] as B operand rows n of WpT (N=1024, K=512)
__global__ void k_pack_T(const float* __restrict__ Wproj, float* __restrict__ dst) {
    int i = blockIdx.x * blockDim.x + threadIdx.x;   // over 1024*512
    if (i < HH * OO) {
        int n = i >> 9, o = i & 511;
        float v = tf32t(Wproj[(size_t)o * HH + n]);
        size_t d = ((size_t)(n >> 7) * 8 + (o >> 6)) * GA + (n & 127) * 68 + (o & 63);
        dst[d] = v;
    }
}
// pack W [4H][H] -> rec layout [nt=64][kc=32][row=64][36(pad)] truncated
__global__ void k_pack_wrec(const float* __restrict__ W, float* __restrict__ Wpk) {
    int i = blockIdx.x * blockDim.x + threadIdx.x;   // 4.19M
    if (i < 64 * 32 * 64 * 32) {
        int k = i & 31, row = (i >> 5) & 63, kc = (i >> 11) & 31, nt = i >> 16;
        int gr = (row >> 4) * HH + nt * 16 + (row & 15);
        Wpk[(((size_t)nt * 32 + kc) * 64 + row) * 36 + k] =
            tf32t(W[(size_t)gr * HH + kc * 32 + k]);
    }
}

// ---------------- bulk-fed pipelined GEMM on packed operands ----------------
// C = A * B^T, 128x128 tile, K-chunk 64, 2-stage, ONE bulk per operand per stage.
// mode 1: packed-P store (+bias). mode 2: final out remap (+bias). mode 3: Weff->rec-pack (+addm).
__global__ void __launch_bounds__(256) k_gemmB(
        const float* __restrict__ Apk, const float* __restrict__ Bpk,
        float* __restrict__ C, int ldc, int K,
        const float* __restrict__ bias, const float* __restrict__ addm, int mode) {
    extern __shared__ float sm[];
    unsigned sbase = (unsigned)__cvta_generic_to_shared(sm);
    unsigned barb  = sbase + 4 * GA * 4;
    const int tid = threadIdx.x;
    const int m0 = blockIdx.y * 128, n0 = blockIdx.x * 128;
    const int w = tid >> 5, wm = w >> 1, wn = w & 1;
    const int nKc = K >> 6;

    if (tid < 2) mbar_init(barb + tid * 8, 1);
    __syncthreads();
    if (tid == 0) fence_async();
    __syncthreads();

    auto issue = [&](int i) {
        if (tid == 0) {
            int st = i & 1;
            mbar_expect(barb + st * 8, 2 * GA * 4);
            bulk_g2s(sbase + (unsigned)(st * GA) * 4,
                     Apk + ((size_t)blockIdx.y * nKc + i) * GA, GA * 4, barb + st * 8);
            bulk_g2s(sbase + (unsigned)((2 + st) * GA) * 4,
                     Bpk + ((size_t)blockIdx.x * nKc + i) * GA, GA * 4, barb + st * 8);
        }
    };

    wmma::fragment<wmma::accumulator, 16, 16, 8, float> acc[2][4];
    #pragma unroll
    for (int i = 0; i < 2; i++)
        #pragma unroll
        for (int j = 0; j < 4; j++) wmma::fill_fragment(acc[i][j], 0.f);

    issue(0);
    if (nKc > 1) issue(1);

    for (int it = 0; it < nKc; it++) {
        int st = it & 1;
        mbar_wait(barb + st * 8, (it >> 1) & 1);
        const float* a = sm + st * GA;
        const float* b = sm + (2 + st) * GA;
        #pragma unroll
        for (int kk = 0; kk < 8; kk++) {
            wmma::fragment<wmma::matrix_a, 16, 16, 8, wmma::precision::tf32, wmma::row_major> a0, a1;
            wmma::fragment<wmma::matrix_b, 16, 16, 8, wmma::precision::tf32, wmma::col_major> bf[4];
            wmma::load_matrix_sync(a0, &a[(wm * 32) * 68 + kk * 8], 68);
            wmma::load_matrix_sync(a1, &a[(wm * 32 + 16) * 68 + kk * 8], 68);
            #pragma unroll
            for (int t = 0; t < 4; t++)
                wmma::load_matrix_sync(bf[t], &b[(wn * 64 + t * 16) * 68 + kk * 8], 68);
            #pragma unroll
            for (int t = 0; t < 4; t++) {
                wmma::mma_sync(acc[0][t], a0, bf[t], acc[0][t]);
                wmma::mma_sync(acc[1][t], a1, bf[t], acc[1][t]);
            }
        }
        __syncthreads();
        if (it + 2 < nKc) issue(it + 2);
    }

    float* sC = sm;   // union with stage buffers
    #pragma unroll
    for (int i = 0; i < 2; i++)
        #pragma unroll
        for (int t = 0; t < 4; t++)
            wmma::store_matrix_sync(&sC[(wm * 32 + i * 16) * 132 + wn * 64 + t * 16],
                                    acc[i][t], 132, wmma::mem_row_major);
    __syncthreads();

    for (int idx = tid; idx < 128 * 128; idx += 256) {
        int m = idx >> 7, n = idx & 127;
        float v = sC[m * 132 + n];
        if (bias) v += bias[n0 + n];
        if (mode == 1) {            // packed-P: r = b*256+s, col = g*1024+c
            int r = m0 + m, ng = n0 + n;
            int bb = r >> 8, s = r & 255;
            int g = ng >> 10, cc = ng & 1023, nt2 = cc >> 4, jj = cc & 15;
            size_t d = (((size_t)s * 128 + nt2 * 2 + (bb >> 6)) * 64 + (bb & 63)) * 64
                       + g * 16 + jj;
            C[d] = v;
        } else if (mode == 2) {     // final: r = t*128+b -> out[b][t][n]
            int r = m0 + m; int b = r & 127, t = r >> 7;
            C[((size_t)b * TT + t) * OO + n0 + n] = v;
        } else {                    // mode 3: Weff -> rec-packed WpkF (+Whh_d)
            int gr = m0 + m, k = n0 + n;
            v += addm[(size_t)gr * ldc + k];
            int g = gr >> 10, cc = gr & 1023, nt2 = cc >> 4, row = g * 16 + (cc & 15);
            C[(((size_t)nt2 * 32 + (k >> 5)) * 64 + row) * 36 + (k & 31)] = tf32t(v);
        }
    }
}

// ---------------- persistent recurrence ----------------
// smem (floats): sA 4x[32][68] | sB 4x[64][36] | sC [64][68] | sP 4096 | sT 1024 | bars
#define R_B   (4 * 2176)
#define R_C   (R_B + 4 * 2304)
#define R_P   (R_C + 4352)
#define R_T   (R_P + 4096)
#define R_FL  (R_T + 1024)
#define R_BARB (R_FL * 4)
#define R_SMEM (R_BARB + 64)

__global__ void __launch_bounds__(256, 1) k_rec(
        const float* __restrict__ Ppk,
        const float* __restrict__ WpkE,
        const float* __restrict__ WpkD,
        const float* __restrict__ WpkF,
        const float* __restrict__ bdec,
        const float* __restrict__ beff,
        float* __restrict__ hT,
        float* __restrict__ Hallpk) {
    extern __shared__ float sm[];
    float* sA = sm;
    float* sB = sm + R_B;
    float* sC = sm + R_C;
    float* sP = sm + R_P;
    float* sT = sm + R_T;
    unsigned sbase = (unsigned)__cvta_generic_to_shared(sm);
    unsigned barb  = sbase + R_BARB;

    const int tid = threadIdx.x, cta = blockIdx.x;
    const int mt = cta & 1, nt = cta >> 1;
    const int m0 = mt * 64, nb = nt * 16;
    const int w = tid >> 5, wm = w >> 1, wn = w & 1;

    if (tid < 5) mbar_init(barb + tid * 8, 1);
    for (int i = tid; i < 1024; i += 256) sT[i] = 0.f;
    __syncthreads();
    if (tid == 0) fence_async();
    __syncthreads();

    int epoch = 0;

    for (int s = 0; s < NSTEP; s++) {
        const float* Wp = (s < SS) ? WpkE : ((s == SS) ? WpkD : WpkF);
        const float* Asrc = hT + (size_t)((s & 1) * 2 + mt) * (32 * 2176);
        float* hTn = hT + (size_t)(((s + 1) & 1) * 2 + mt) * (32 * 2176);

        if (tid == 0) {
            if (s < SS) {
                mbar_expect(barb + 32, 16384);
                bulk_g2s(sbase + R_P * 4, Ppk + ((size_t)s * 128 + cta) * 4096,
                         16384, barb + 32);
            }
            #pragma unroll
            for (int p = 0; p < 4; p++) {
                mbar_expect(barb + p * 8, 8704 + 9216);
                bulk_g2s(sbase + (unsigned)(p * 2176) * 4,
                         Asrc + (size_t)p * 2176, 8704, barb + p * 8);
                bulk_g2s(sbase + (unsigned)(R_B + p * 2304) * 4,
                         Wp + ((size_t)nt * 32 + p) * 2304, 9216, barb + p * 8);
            }
        }

        wmma::fragment<wmma::accumulator, 16, 16, 8, float> c0, c1;
        wmma::fill_fragment(c0, 0.f);
        wmma::fill_fragment(c1, 0.f);

        for (int i = 0; i < 32; i++) {
            int st = i & 3;
            mbar_wait(barb + st * 8, (i >> 2) & 1);
            const float* a = sA + st * 2176;   // [k=32][m=68ld]
            const float* b = sB + st * 2304;   // [row=64][k=36ld]
            #pragma unroll
            for (int kk = 0; kk < 4; kk++) {
                wmma::fragment<wmma::matrix_a, 16, 16, 8, wmma::precision::tf32, wmma::col_major> af;
                wmma::fragment<wmma::matrix_b, 16, 16, 8, wmma::precision::tf32, wmma::col_major> b0, b1;
                wmma::load_matrix_sync(af, &a[kk * 8 * 68 + wm * 16], 68);
                wmma::load_matrix_sync(b0, &b[(wn * 32) * 36 + kk * 8], 36);
                wmma::load_matrix_sync(b1, &b[(wn * 32 + 16) * 36 + kk * 8], 36);
                wmma::mma_sync(c0, af, b0, c0);
                wmma::mma_sync(c1, af, b1, c1);
            }
            __syncthreads();
            if (tid == 0 && i + 4 < 32) {
                mbar_expect(barb + st * 8, 8704 + 9216);
                bulk_g2s(sbase + (unsigned)(st * 2176) * 4,
                         Asrc + (size_t)(i + 4) * 2176, 8704, barb + st * 8);
                bulk_g2s(sbase + (unsigned)(R_B + st * 2304) * 4,
                         Wp + ((size_t)nt * 32 + (i + 4)) * 2304, 9216, barb + st * 8);
            }
        }

        wmma::store_matrix_sync(&sC[wm * 16 * 68 + wn * 32],      c0, 68, wmma::mem_row_major);
        wmma::store_matrix_sync(&sC[wm * 16 * 68 + wn * 32 + 16], c1, 68, wmma::mem_row_major);
        __syncthreads();

        if (s < SS) mbar_wait(barb + 32, s & 1);

        const float* gb = (s == SS) ? bdec : beff;
        for (int idx = tid; idx < 1024; idx += 256) {
            int m = idx >> 4, j = idx & 15;    // j minor: kills sP bank conflict
            float ai, af_, ag, ao;
            if (s < SS) {
                ai = sP[m * 64 + j];       af_ = sP[m * 64 + 16 + j];
                ag = sP[m * 64 + 32 + j];  ao  = sP[m * 64 + 48 + j];
            } else {
                ai = gb[nb + j];           af_ = gb[HH + nb + j];
                ag = gb[2 * HH + nb + j];  ao  = gb[3 * HH + nb + j];
            }
            float gi = sC[m * 68 + j]      + ai;
            float gf = sC[m * 68 + 16 + j] + af_;
            float gg = sC[m * 68 + 32 + j] + ag;
            float go = sC[m * 68 + 48 + j] + ao;
            float co = sT[m * 16 + j];
            float si = 1.f / (1.f + expf(-gi));
            float sf = 1.f / (1.f + expf(-gf));
            float so = 1.f / (1.f + expf(-go));
            float cn = sf * co + si * tanhf(gg);
            float hn = so * tanhf(cn);
            sT[m * 16 + j] = cn;
            float hnt = tf32t(hn);
            int n = nb + j;
            hTn[(size_t)(n >> 5) * 2176 + (n & 31) * 68 + m] = hnt;
            if (s >= SS) {
                int t = s - SS;
                Hallpk[(((size_t)t * 16 + (n >> 6)) * 128 + m0 + m) * 68 + (n & 63)] = hnt;
            }
        }

        if (s < NSTEP - 1) gridbar(epoch);
    }
}

// ---------------- host launch ----------------
extern "C" void kernel_launch(void* const* d_in, const int* in_sizes, int n_in,
                              void* d_out, int out_size) {
    int wbase = (n_in >= 12 && in_sizes[1] == 1) ? 2 : 1;

    const float* x     = (const float*)d_in[0];
    const float* Wih_e = (const float*)d_in[wbase + 0];
    const float* Whh_e = (const float*)d_in[wbase + 1];
    const float* bih_e = (const float*)d_in[wbase + 2];
    const float* bhh_e = (const float*)d_in[wbase + 3];
    const float* Wih_d = (const float*)d_in[wbase + 4];
    const float* Whh_d = (const float*)d_in[wbase + 5];
    const float* bih_d = (const float*)d_in[wbase + 6];
    const float* bhh_d = (const float*)d_in[wbase + 7];
    const float* Wproj = (const float*)d_in[wbase + 8];
    const float* bproj = (const float*)d_in[wbase + 9];
    float* out = (float*)d_out;

    float *Ppk, *xpk, *WihEpk, *WihDpk, *WpTpk, *Wprojpk, *Hallpk;
    float *WpkE, *WpkD, *WpkF, *hT, *benc, *bdec, *beff;
    cudaGetSymbolAddress((void**)&Ppk,     g_Ppk);
    cudaGetSymbolAddress((void**)&xpk,     g_xpk);
    cudaGetSymbolAddress((void**)&WihEpk,  g_WihEpk);
    cudaGetSymbolAddress((void**)&WihDpk,  g_WihDpk);
    cudaGetSymbolAddress((void**)&WpTpk,   g_WpTpk);
    cudaGetSymbolAddress((void**)&Wprojpk, g_Wprojpk);
    cudaGetSymbolAddress((void**)&Hallpk,  g_Hallpk);
    cudaGetSymbolAddress((void**)&WpkE,    g_WpkE);
    cudaGetSymbolAddress((void**)&WpkD,    g_WpkD);
    cudaGetSymbolAddress((void**)&WpkF,    g_WpkF);
    cudaGetSymbolAddress((void**)&hT,      g_hT);
    cudaGetSymbolAddress((void**)&benc,    g_benc);
    cudaGetSymbolAddress((void**)&bdec,    g_bdec);
    cudaGetSymbolAddress((void**)&beff,    g_beff);

    const int gemmSmem = 4 * GA * 4 + 64;
    cudaFuncSetAttribute(k_gemmB, cudaFuncAttributeMaxDynamicSharedMemorySize, gemmSmem);
    cudaFuncSetAttribute(k_rec,   cudaFuncAttributeMaxDynamicSharedMemorySize, R_SMEM);

    // biases
    k_vec_add<<<16, 256>>>(bih_e, bhh_e, benc, G4H);
    k_vec_add<<<16, 256>>>(bih_d, bhh_d, bdec, G4H);
    k_beff<<<16, 256>>>(Wih_d, bproj, bdec, beff);

    // packs
    k_pack<<<(int)(((size_t)BB * SS * II / 4 + 255) / 256), 256>>>(
        x, xpk, II, (size_t)BB * SS * II);
    k_pack<<<(int)(((size_t)G4H * II / 4 + 255) / 256), 256>>>(
        Wih_e, WihEpk, II, (size_t)G4H * II);
    k_pack<<<(int)(((size_t)G4H * OO / 4 + 255) / 256), 256>>>(
        Wih_d, WihDpk, OO, (size_t)G4H * OO);
    k_pack<<<(int)(((size_t)OO * HH / 4 + 255) / 256), 256>>>(
        Wproj, Wprojpk, HH, (size_t)OO * HH);
    k_pack_T<<<(HH * OO + 255) / 256, 256>>>(Wproj, WpTpk);
    k_pack_wrec<<<(64 * 32 * 64 * 32) / 256, 256>>>(Whh_e, WpkE);
    k_pack_wrec<<<(64 * 32 * 64 * 32) / 256, 256>>>(Whh_d, WpkD);

    // W_eff = W_ih_dec @ W_proj + W_hh_dec -> rec-packed WpkF (mode 3)
    k_gemmB<<<dim3(HH / 128, G4H / 128), 256, gemmSmem>>>(
        WihDpk, WpTpk, WpkF, HH, OO, nullptr, Whh_d, 3);

    // P = X @ W_ih_enc^T + b_enc -> packed Ppk (mode 1)
    k_gemmB<<<dim3(G4H / 128, (BB * SS) / 128), 256, gemmSmem>>>(
        xpk, WihEpk, Ppk, 0, II, benc, nullptr, 1);

    // zero h buffer 0, reset barrier, run the 384-step recurrence
    k_zero<<<(2 * 2 * 32 * 32 * 68 + 255) / 256, 256>>>(hT, 2 * 2 * 32 * 32 * 68);
    k_reset_bar<<<1, 1>>>();
    k_rec<<<NCTA_REC, 256, R_SMEM>>>(Ppk, WpkE, WpkD, WpkF, bdec, beff, hT, Hallpk);

    // Y = Hall @ W_proj^T + b_proj -> out[b][t][o] (mode 2)
    k_gemmB<<<dim3(OO / 128, (BB * TT) / 128), 256, gemmSmem>>>(
        Hallpk, Wprojpk, out, 0, HH, bproj, nullptr, 2);
}

// round 7
// speedup vs baseline: 1.0830x; 1.0830x over previous
#include <cuda_runtime.h>
#include <mma.h>
#include <math.h>

using namespace nvcuda;

#define BB  128
#define SS  256
#define II  512
#define HH  1024
#define OO  512
#define TT  128
#define G4H 4096
#define NSTEP (SS + TT)
#define NCTA_REC 128
#define GA 8704            // floats per packed 128x68 K-chunk tile

// ---------------- static device scratch ----------------
__device__ __align__(128) float g_Ppk[(size_t)SS * 128 * 4096];     // packed P (512MB)
__device__ __align__(128) float g_xpk[(size_t)256 * 8 * GA];        // packed x
__device__ __align__(128) float g_WihEpk[(size_t)32 * 8 * GA];
__device__ __align__(128) float g_WihDpk[(size_t)32 * 8 * GA];
__device__ __align__(128) float g_WpTpk[(size_t)8 * 8 * GA];
__device__ __align__(128) float g_Wprojpk[(size_t)4 * 16 * GA];
__device__ __align__(128) float g_Hallpk[(size_t)128 * 16 * GA];    // decoder h, packed
__device__ __align__(128) float g_WpkE[64 * 32 * 64 * 36];          // rec-packed weights (pad 36)
__device__ __align__(128) float g_WpkD[64 * 32 * 64 * 36];
__device__ __align__(128) float g_WpkF[64 * 32 * 64 * 36];
__device__ __align__(128) float g_hT[2 * 2 * 32 * 32 * 68];         // double-buffered transposed h
__device__ float g_benc[G4H];
__device__ float g_bdec[G4H];
__device__ float g_beff[G4H];
__device__ unsigned g_bar;

// ---------------- helpers ----------------
__device__ __forceinline__ float tf32t(float x) {
    unsigned u;
    asm("cvt.rna.tf32.f32 %0, %1;" : "=r"(u) : "f"(x));
    return __uint_as_float(u);
}
__device__ __forceinline__ void mbar_init(unsigned mbar, unsigned cnt) {
    asm volatile("mbarrier.init.shared.b64 [%0], %1;" :: "r"(mbar), "r"(cnt) : "memory");
}
__device__ __forceinline__ void mbar_expect(unsigned mbar, unsigned bytes) {
    asm volatile("mbarrier.arrive.expect_tx.shared.b64 _, [%0], %1;"
                 :: "r"(mbar), "r"(bytes) : "memory");
}
__device__ __forceinline__ void mbar_wait(unsigned mbar, unsigned parity) {
    unsigned done = 0;
    while (!done) {
        asm volatile(
            "{\n\t.reg .pred p;\n\t"
            "mbarrier.try_wait.parity.acquire.cta.shared::cta.b64 p, [%1], %2, 0x989680;\n\t"
            "selp.b32 %0, 1, 0, p;\n\t}"
            : "=r"(done) : "r"(mbar), "r"(parity) : "memory");
    }
}
__device__ __forceinline__ void bulk_g2s(unsigned dst, const void* src, unsigned bytes,
                                         unsigned mbar) {
    asm volatile(
        "cp.async.bulk.shared::cluster.global.mbarrier::complete_tx::bytes [%0], [%1], %2, [%3];"
        :: "r"(dst), "l"(src), "r"(bytes), "r"(mbar) : "memory");
}
__device__ __forceinline__ void fence_async() {
    asm volatile("fence.proxy.async.shared::cta;" ::: "memory");
}

// ---------------- grid barrier ----------------
__device__ __forceinline__ void gridbar(int& epoch) {
    epoch++;
    __threadfence();
    __syncthreads();
    if (threadIdx.x == 0) {
        atomicAdd(&g_bar, 1u);
        const unsigned tgt = (unsigned)NCTA_REC * (unsigned)epoch;
        volatile unsigned* p = &g_bar;
        while (*p < tgt) { }
    }
    __syncthreads();
}
__global__ void k_reset_bar() { g_bar = 0u; }

// ---------------- small kernels ----------------
__global__ void k_zero(float* p, int n) {
    int i = blockIdx.x * blockDim.x + threadIdx.x;
    if (i < n) p[i] = 0.f;
}
__global__ void k_vec_add(const float* __restrict__ a, const float* __restrict__ b,
                          float* __restrict__ o, int n) {
    int i = blockIdx.x * blockDim.x + threadIdx.x;
    if (i < n) o[i] = a[i] + b[i];
}
__global__ void k_beff(const float* __restrict__ Wih, const float* __restrict__ bproj,
                       const float* __restrict__ bdec, float* __restrict__ beff) {
    int n = blockIdx.x * blockDim.x + threadIdx.x;
    if (n < G4H) {
        float s = bdec[n];
        const float* wr = Wih + (size_t)n * OO;
        #pragma unroll 8
        for (int o = 0; o < OO; o++) s += wr[o] * bproj[o];
        beff[n] = s;
    }
}
// generic pack: src [M][K] row-major -> dst [mtile][kc][128][68], tf32-truncated
__global__ void k_pack(const float* __restrict__ src, float* __restrict__ dst,
                       int K, size_t total) {
    size_t i = ((size_t)blockIdx.x * 256 + threadIdx.x) * 4;
    if (i < total) {
        int r = (int)(i / (unsigned)K);
        int k = (int)(i - (size_t)r * K);
        float4 v = *(const float4*)&src[i];
        v.x = tf32t(v.x); v.y = tf32t(v.y); v.z = tf32t(v.z); v.w = tf32t(v.w);
        int nk = K >> 6;
        size_t d = ((size_t)(r >> 7) * nk + (k >> 6)) * GA + (r & 127) * 68 + (k & 63);
        *(float4*)&dst[d] = v;
    }
}
// pack transpose of Wproj [O=512][H=1024] as B operand rows n of WpT (N=1024, K=512)
__global__ void k_pack_T(const float* __restrict__ Wproj, float* __restrict__ dst) {
    int i = blockIdx.x * blockDim.x + threadIdx.x;   // over 1024*512
    if (i < HH * OO) {
        int n = i >> 9, o = i & 511;
        float v = tf32t(Wproj[(size_t)o * HH + n]);
        size_t d = ((size_t)(n >> 7) * 8 + (o >> 6)) * GA + (n & 127) * 68 + (o & 63);
        dst[d] = v;
    }
}
// pack W [4H][H] -> rec layout [nt=64][kc=32][row=64][36(pad)] truncated
__global__ void k_pack_wrec(const float* __restrict__ W, float* __restrict__ Wpk) {
    int i = blockIdx.x * blockDim.x + threadIdx.x;   // 4.19M
    if (i < 64 * 32 * 64 * 32) {
        int k = i & 31, row = (i >> 5) & 63, kc = (i >> 11) & 31, nt = i >> 16;
        int gr = (row >> 4) * HH + nt * 16 + (row & 15);
        Wpk[(((size_t)nt * 32 + kc) * 64 + row) * 36 + k] =
            tf32t(W[(size_t)gr * HH + kc * 32 + k]);
    }
}

// ---------------- bulk-fed pipelined GEMM on packed operands ----------------
// C = A * B^T, 128x128 tile, K-chunk 64, 2-stage, ONE bulk per operand per stage.
// mode 1: packed-P store (+bias). mode 2: final out remap (+bias). mode 3: Weff->rec-pack (+addm).
__global__ void __launch_bounds__(256) k_gemmB(
        const float* __restrict__ Apk, const float* __restrict__ Bpk,
        float* __restrict__ C, int ldc, int K,
        const float* __restrict__ bias, const float* __restrict__ addm, int mode) {
    extern __shared__ float sm[];
    unsigned sbase = (unsigned)__cvta_generic_to_shared(sm);
    unsigned barb  = sbase + 4 * GA * 4;
    const int tid = threadIdx.x;
    const int m0 = blockIdx.y * 128, n0 = blockIdx.x * 128;
    const int w = tid >> 5, wm = w >> 1, wn = w & 1;
    const int nKc = K >> 6;

    if (tid < 2) mbar_init(barb + tid * 8, 1);
    __syncthreads();
    if (tid == 0) fence_async();
    __syncthreads();

    auto issue = [&](int i) {
        if (tid == 0) {
            int st = i & 1;
            mbar_expect(barb + st * 8, 2 * GA * 4);
            bulk_g2s(sbase + (unsigned)(st * GA) * 4,
                     Apk + ((size_t)blockIdx.y * nKc + i) * GA, GA * 4, barb + st * 8);
            bulk_g2s(sbase + (unsigned)((2 + st) * GA) * 4,
                     Bpk + ((size_t)blockIdx.x * nKc + i) * GA, GA * 4, barb + st * 8);
        }
    };

    wmma::fragment<wmma::accumulator, 16, 16, 8, float> acc[2][4];
    #pragma unroll
    for (int i = 0; i < 2; i++)
        #pragma unroll
        for (int j = 0; j < 4; j++) wmma::fill_fragment(acc[i][j], 0.f);

    issue(0);
    if (nKc > 1) issue(1);

    for (int it = 0; it < nKc; it++) {
        int st = it & 1;
        mbar_wait(barb + st * 8, (it >> 1) & 1);
        const float* a = sm + st * GA;
        const float* b = sm + (2 + st) * GA;
        #pragma unroll
        for (int kk = 0; kk < 8; kk++) {
            wmma::fragment<wmma::matrix_a, 16, 16, 8, wmma::precision::tf32, wmma::row_major> a0, a1;
            wmma::fragment<wmma::matrix_b, 16, 16, 8, wmma::precision::tf32, wmma::col_major> bf[4];
            wmma::load_matrix_sync(a0, &a[(wm * 32) * 68 + kk * 8], 68);
            wmma::load_matrix_sync(a1, &a[(wm * 32 + 16) * 68 + kk * 8], 68);
            #pragma unroll
            for (int t = 0; t < 4; t++)
                wmma::load_matrix_sync(bf[t], &b[(wn * 64 + t * 16) * 68 + kk * 8], 68);
            #pragma unroll
            for (int t = 0; t < 4; t++) {
                wmma::mma_sync(acc[0][t], a0, bf[t], acc[0][t]);
                wmma::mma_sync(acc[1][t], a1, bf[t], acc[1][t]);
            }
        }
        __syncthreads();
        if (it + 2 < nKc) issue(it + 2);
    }

    float* sC = sm;   // union with stage buffers
    #pragma unroll
    for (int i = 0; i < 2; i++)
        #pragma unroll
        for (int t = 0; t < 4; t++)
            wmma::store_matrix_sync(&sC[(wm * 32 + i * 16) * 132 + wn * 64 + t * 16],
                                    acc[i][t], 132, wmma::mem_row_major);
    __syncthreads();

    for (int idx = tid; idx < 128 * 128; idx += 256) {
        int m = idx >> 7, n = idx & 127;
        float v = sC[m * 132 + n];
        if (bias) v += bias[n0 + n];
        if (mode == 1) {            // packed-P: r = b*256+s, col = g*1024+c
            int r = m0 + m, ng = n0 + n;
            int bb = r >> 8, s = r & 255;
            int g = ng >> 10, cc = ng & 1023, nt2 = cc >> 4, jj = cc & 15;
            size_t d = (((size_t)s * 128 + nt2 * 2 + (bb >> 6)) * 64 + (bb & 63)) * 64
                       + g * 16 + jj;
            C[d] = v;
        } else if (mode == 2) {     // final: r = t*128+b -> out[b][t][n]
            int r = m0 + m; int b = r & 127, t = r >> 7;
            C[((size_t)b * TT + t) * OO + n0 + n] = v;
        } else {                    // mode 3: Weff -> rec-packed WpkF (+Whh_d)
            int gr = m0 + m, k = n0 + n;
            v += addm[(size_t)gr * ldc + k];
            int g = gr >> 10, cc = gr & 1023, nt2 = cc >> 4, row = g * 16 + (cc & 15);
            C[(((size_t)nt2 * 32 + (k >> 5)) * 64 + row) * 36 + (k & 31)] = tf32t(v);
        }
    }
}

// ---------------- persistent recurrence: 8 x k=128 chunks, 2-stage bulk pipeline ----
// smem (floats): sA 2x8704 | sB 2x9216 | sC 4352 | sP 4096 | sT 1024 | bars
#define R_B    17408
#define R_C    35840
#define R_P    40192
#define R_T    44288
#define R_FL   45312
#define R_BARB (R_FL * 4)
#define R_SMEM (R_BARB + 64)

__global__ void __launch_bounds__(256, 1) k_rec(
        const float* __restrict__ Ppk,
        const float* __restrict__ WpkE,
        const float* __restrict__ WpkD,
        const float* __restrict__ WpkF,
        const float* __restrict__ bdec,
        const float* __restrict__ beff,
        float* __restrict__ hT,
        float* __restrict__ Hallpk) {
    extern __shared__ float sm[];
    float* sA = sm;
    float* sB = sm + R_B;
    float* sC = sm + R_C;
    float* sP = sm + R_P;
    float* sT = sm + R_T;
    unsigned sbase = (unsigned)__cvta_generic_to_shared(sm);
    unsigned barb  = sbase + R_BARB;

    const int tid = threadIdx.x, cta = blockIdx.x;
    const int mt = cta & 1, nt = cta >> 1;
    const int m0 = mt * 64, nb = nt * 16;
    const int w = tid >> 5, wm = w >> 1, wn = w & 1;

    if (tid < 3) mbar_init(barb + tid * 8, 1);       // 0,1: stages; 2: P
    for (int i = tid; i < 1024; i += 256) sT[i] = 0.f;
    __syncthreads();
    if (tid == 0) fence_async();
    __syncthreads();

    int epoch = 0;

    for (int s = 0; s < NSTEP; s++) {
        const float* Wp = (s < SS) ? WpkE : ((s == SS) ? WpkD : WpkF);
        const float* Asrc = hT + (size_t)((s & 1) * 2 + mt) * (32 * 2176);
        float* hTn = hT + (size_t)(((s + 1) & 1) * 2 + mt) * (32 * 2176);

        auto issue = [&](int c) {      // chunk c covers kc 4c..4c+3
            int st = c & 1;
            mbar_expect(barb + st * 8, 34816 + 36864);
            bulk_g2s(sbase + (unsigned)(st * 8704) * 4,
                     Asrc + (size_t)c * 8704, 34816, barb + st * 8);
            bulk_g2s(sbase + (unsigned)(R_B + st * 9216) * 4,
                     Wp + ((size_t)nt * 32 + c * 4) * 2304, 36864, barb + st * 8);
        };

        if (tid == 0) {
            if (s < SS) {
                mbar_expect(barb + 16, 16384);
                bulk_g2s(sbase + R_P * 4, Ppk + ((size_t)s * 128 + cta) * 4096,
                         16384, barb + 16);
            }
            issue(0);
            issue(1);
        }

        wmma::fragment<wmma::accumulator, 16, 16, 8, float> c0, c1;
        wmma::fill_fragment(c0, 0.f);
        wmma::fill_fragment(c1, 0.f);

        for (int c = 0; c < 8; c++) {
            int st = c & 1;
            mbar_wait(barb + st * 8, (c >> 1) & 1);
            #pragma unroll
            for (int sub = 0; sub < 4; sub++) {
                const float* a = sA + st * 8704 + sub * 2176;   // [k=32][m ld=68]
                const float* b = sB + st * 9216 + sub * 2304;   // [row=64][k ld=36]
                #pragma unroll
                for (int kk = 0; kk < 4; kk++) {
                    wmma::fragment<wmma::matrix_a, 16, 16, 8, wmma::precision::tf32, wmma::col_major> af;
                    wmma::fragment<wmma::matrix_b, 16, 16, 8, wmma::precision::tf32, wmma::col_major> b0, b1;
                    wmma::load_matrix_sync(af, &a[kk * 8 * 68 + wm * 16], 68);
                    wmma::load_matrix_sync(b0, &b[(wn * 32) * 36 + kk * 8], 36);
                    wmma::load_matrix_sync(b1, &b[(wn * 32 + 16) * 36 + kk * 8], 36);
                    wmma::mma_sync(c0, af, b0, c0);
                    wmma::mma_sync(c1, af, b1, c1);
                }
            }
            __syncthreads();
            if (tid == 0 && c + 2 < 8) issue(c + 2);
        }

        wmma::store_matrix_sync(&sC[wm * 16 * 68 + wn * 32],      c0, 68, wmma::mem_row_major);
        wmma::store_matrix_sync(&sC[wm * 16 * 68 + wn * 32 + 16], c1, 68, wmma::mem_row_major);
        __syncthreads();

        if (s < SS) mbar_wait(barb + 16, s & 1);

        const float* gb = (s == SS) ? bdec : beff;
        for (int idx = tid; idx < 1024; idx += 256) {
            int m = idx >> 4, j = idx & 15;
            float ai, af_, ag, ao;
            if (s < SS) {
                ai = sP[m * 64 + j];       af_ = sP[m * 64 + 16 + j];
                ag = sP[m * 64 + 32 + j];  ao  = sP[m * 64 + 48 + j];
            } else {
                ai = gb[nb + j];           af_ = gb[HH + nb + j];
                ag = gb[2 * HH + nb + j];  ao  = gb[3 * HH + nb + j];
            }
            float gi = sC[m * 68 + j]      + ai;
            float gf = sC[m * 68 + 16 + j] + af_;
            float gg = sC[m * 68 + 32 + j] + ag;
            float go = sC[m * 68 + 48 + j] + ao;
            float co = sT[m * 16 + j];
            float si = 1.f / (1.f + expf(-gi));
            float sf = 1.f / (1.f + expf(-gf));
            float so = 1.f / (1.f + expf(-go));
            float cn = sf * co + si * tanhf(gg);
            float hn = so * tanhf(cn);
            sT[m * 16 + j] = cn;
            float hnt = tf32t(hn);
            int n = nb + j;
            hTn[(size_t)(n >> 5) * 2176 + (n & 31) * 68 + m] = hnt;
            if (s >= SS) {
                int t = s - SS;
                Hallpk[(((size_t)t * 16 + (n >> 6)) * 128 + m0 + m) * 68 + (n & 63)] = hnt;
            }
        }

        if (s < NSTEP - 1) gridbar(epoch);
    }
}

// ---------------- host launch ----------------
extern "C" void kernel_launch(void* const* d_in, const int* in_sizes, int n_in,
                              void* d_out, int out_size) {
    int wbase = (n_in >= 12 && in_sizes[1] == 1) ? 2 : 1;

    const float* x     = (const float*)d_in[0];
    const float* Wih_e = (const float*)d_in[wbase + 0];
    const float* Whh_e = (const float*)d_in[wbase + 1];
    const float* bih_e = (const float*)d_in[wbase + 2];
    const float* bhh_e = (const float*)d_in[wbase + 3];
    const float* Wih_d = (const float*)d_in[wbase + 4];
    const float* Whh_d = (const float*)d_in[wbase + 5];
    const float* bih_d = (const float*)d_in[wbase + 6];
    const float* bhh_d = (const float*)d_in[wbase + 7];
    const float* Wproj = (const float*)d_in[wbase + 8];
    const float* bproj = (const float*)d_in[wbase + 9];
    float* out = (float*)d_out;

    float *Ppk, *xpk, *WihEpk, *WihDpk, *WpTpk, *Wprojpk, *Hallpk;
    float *WpkE, *WpkD, *WpkF, *hT, *benc, *bdec, *beff;
    cudaGetSymbolAddress((void**)&Ppk,     g_Ppk);
    cudaGetSymbolAddress((void**)&xpk,     g_xpk);
    cudaGetSymbolAddress((void**)&WihEpk,  g_WihEpk);
    cudaGetSymbolAddress((void**)&WihDpk,  g_WihDpk);
    cudaGetSymbolAddress((void**)&WpTpk,   g_WpTpk);
    cudaGetSymbolAddress((void**)&Wprojpk, g_Wprojpk);
    cudaGetSymbolAddress((void**)&Hallpk,  g_Hallpk);
    cudaGetSymbolAddress((void**)&WpkE,    g_WpkE);
    cudaGetSymbolAddress((void**)&WpkD,    g_WpkD);
    cudaGetSymbolAddress((void**)&WpkF,    g_WpkF);
    cudaGetSymbolAddress((void**)&hT,      g_hT);
    cudaGetSymbolAddress((void**)&benc,    g_benc);
    cudaGetSymbolAddress((void**)&bdec,    g_bdec);
    cudaGetSymbolAddress((void**)&beff,    g_beff);

    const int gemmSmem = 4 * GA * 4 + 64;
    cudaFuncSetAttribute(k_gemmB, cudaFuncAttributeMaxDynamicSharedMemorySize, gemmSmem);
    cudaFuncSetAttribute(k_rec,   cudaFuncAttributeMaxDynamicSharedMemorySize, R_SMEM);

    // biases
    k_vec_add<<<16, 256>>>(bih_e, bhh_e, benc, G4H);
    k_vec_add<<<16, 256>>>(bih_d, bhh_d, bdec, G4H);
    k_beff<<<16, 256>>>(Wih_d, bproj, bdec, beff);

    // packs
    k_pack<<<(int)(((size_t)BB * SS * II / 4 + 255) / 256), 256>>>(
        x, xpk, II, (size_t)BB * SS * II);
    k_pack<<<(int)(((size_t)G4H * II / 4 + 255) / 256), 256>>>(
        Wih_e, WihEpk, II, (size_t)G4H * II);
    k_pack<<<(int)(((size_t)G4H * OO / 4 + 255) / 256), 256>>>(
        Wih_d, WihDpk, OO, (size_t)G4H * OO);
    k_pack<<<(int)(((size_t)OO * HH / 4 + 255) / 256), 256>>>(
        Wproj, Wprojpk, HH, (size_t)OO * HH);
    k_pack_T<<<(HH * OO + 255) / 256, 256>>>(Wproj, WpTpk);
    k_pack_wrec<<<(64 * 32 * 64 * 32) / 256, 256>>>(Whh_e, WpkE);
    k_pack_wrec<<<(64 * 32 * 64 * 32) / 256, 256>>>(Whh_d, WpkD);

    // W_eff = W_ih_dec @ W_proj + W_hh_dec -> rec-packed WpkF (mode 3)
    k_gemmB<<<dim3(HH / 128, G4H / 128), 256, gemmSmem>>>(
        WihDpk, WpTpk, WpkF, HH, OO, nullptr, Whh_d, 3);

    // P = X @ W_ih_enc^T + b_enc -> packed Ppk (mode 1)
    k_gemmB<<<dim3(G4H / 128, (BB * SS) / 128), 256, gemmSmem>>>(
        xpk, WihEpk, Ppk, 0, II, benc, nullptr, 1);

    // zero h buffer 0, reset barrier, run the 384-step recurrence
    k_zero<<<(2 * 2 * 32 * 32 * 68 + 255) / 256, 256>>>(hT, 2 * 2 * 32 * 32 * 68);
    k_reset_bar<<<1, 1>>>();
    k_rec<<<NCTA_REC, 256, R_SMEM>>>(Ppk, WpkE, WpkD, WpkF, bdec, beff, hT, Hallpk);

    // Y = Hall @ W_proj^T + b_proj -> out[b][t][o] (mode 2)
    k_gemmB<<<dim3(OO / 128, (BB * TT) / 128), 256, gemmSmem>>>(
        Hallpk, Wprojpk, out, 0, HH, bproj, nullptr, 2);
}

// round 8
// speedup vs baseline: 1.8063x; 1.6678x over previous
#include <cuda_runtime.h>
#include <cuda_fp16.h>
#include <mma.h>
#include <math.h>

using namespace nvcuda;

#define BB  128
#define SS  256
#define II  512
#define HH  1024
#define OO  512
#define TT  128
#define G4H 4096
#define NSTEP (SS + TT)
#define NCTA_REC 128
#define GA 8704            // floats per packed 128x68 K-chunk tile (tf32 GEMM)

// ---------------- static device scratch ----------------
__device__ __align__(128) float g_Ppk[(size_t)SS * 128 * 4096];   // P [s][cta][col64][m64]
__device__ __align__(128) float g_xpk[(size_t)256 * 8 * GA];
__device__ __align__(128) float g_WihEpk[(size_t)32 * 8 * GA];
__device__ __align__(128) float g_WihDpk[(size_t)32 * 8 * GA];
__device__ __align__(128) float g_WpTpk[(size_t)8 * 8 * GA];
__device__ __align__(128) float g_Wprojpk[(size_t)4 * 16 * GA];
__device__ __align__(128) float g_Hallpk[(size_t)128 * 16 * GA];
__device__ __align__(128) __half g_Wt16E[(size_t)64 * 8 * 8704]; // [nt][ch][64r][136k]
__device__ __align__(128) __half g_Wt16D[(size_t)64 * 8 * 8704];
__device__ __align__(128) __half g_Wt16F[(size_t)64 * 8 * 8704];
__device__ __align__(128) __half g_hT16[2 * 2 * 8 * 128 * 72];   // [buf][mt][ch][128k][72m]
__device__ float g_benc[G4H];
__device__ float g_bdec[G4H];
__device__ float g_beff[G4H];
__device__ unsigned g_bar2[2];

// ---------------- helpers ----------------
__device__ __forceinline__ float tf32t(float x) {
    unsigned u;
    asm("cvt.rna.tf32.f32 %0, %1;" : "=r"(u) : "f"(x));
    return __uint_as_float(u);
}
__device__ __forceinline__ void mbar_init(unsigned mbar, unsigned cnt) {
    asm volatile("mbarrier.init.shared.b64 [%0], %1;" :: "r"(mbar), "r"(cnt) : "memory");
}
__device__ __forceinline__ void mbar_expect(unsigned mbar, unsigned bytes) {
    asm volatile("mbarrier.arrive.expect_tx.shared.b64 _, [%0], %1;"
                 :: "r"(mbar), "r"(bytes) : "memory");
}
__device__ __forceinline__ void mbar_wait(unsigned mbar, unsigned parity) {
    unsigned done = 0;
    while (!done) {
        asm volatile(
            "{\n\t.reg .pred p;\n\t"
            "mbarrier.try_wait.parity.acquire.cta.shared::cta.b64 p, [%1], %2, 0x989680;\n\t"
            "selp.b32 %0, 1, 0, p;\n\t}"
            : "=r"(done) : "r"(mbar), "r"(parity) : "memory");
    }
}
__device__ __forceinline__ void bulk_g2s(unsigned dst, const void* src, unsigned bytes,
                                         unsigned mbar) {
    asm volatile(
        "cp.async.bulk.shared::cluster.global.mbarrier::complete_tx::bytes [%0], [%1], %2, [%3];"
        :: "r"(dst), "l"(src), "r"(bytes), "r"(mbar) : "memory");
}

// ---------------- dual grid barrier (per-mt groups of 64 CTAs) ----------------
__device__ __forceinline__ void gridbar2(int mt, int& epoch) {
    epoch++;
    __threadfence();
    __syncthreads();
    if (threadIdx.x == 0) {
        atomicAdd(&g_bar2[mt], 1u);
        const unsigned tgt = 64u * (unsigned)epoch;
        volatile unsigned* p = &g_bar2[mt];
        while (*p < tgt) { }
    }
    __syncthreads();
}
__global__ void k_reset_bar() { g_bar2[0] = 0u; g_bar2[1] = 0u; }

// ---------------- small kernels ----------------
__global__ void k_zero(float* p, int n) {
    int i = blockIdx.x * blockDim.x + threadIdx.x;
    if (i < n) p[i] = 0.f;
}
__global__ void k_vec_add(const float* __restrict__ a, const float* __restrict__ b,
                          float* __restrict__ o, int n) {
    int i = blockIdx.x * blockDim.x + threadIdx.x;
    if (i < n) o[i] = a[i] + b[i];
}
__global__ void k_beff(const float* __restrict__ Wih, const float* __restrict__ bproj,
                       const float* __restrict__ bdec, float* __restrict__ beff) {
    int n = blockIdx.x * blockDim.x + threadIdx.x;
    if (n < G4H) {
        float s = bdec[n];
        const float* wr = Wih + (size_t)n * OO;
        #pragma unroll 8
        for (int o = 0; o < OO; o++) s += wr[o] * bproj[o];
        beff[n] = s;
    }
}
// generic pack: src [M][K] row-major -> dst [mtile][kc][128][68], tf32-truncated
__global__ void k_pack(const float* __restrict__ src, float* __restrict__ dst,
                       int K, size_t total) {
    size_t i = ((size_t)blockIdx.x * 256 + threadIdx.x) * 4;
    if (i < total) {
        int r = (int)(i / (unsigned)K);
        int k = (int)(i - (size_t)r * K);
        float4 v = *(const float4*)&src[i];
        v.x = tf32t(v.x); v.y = tf32t(v.y); v.z = tf32t(v.z); v.w = tf32t(v.w);
        int nk = K >> 6;
        size_t d = ((size_t)(r >> 7) * nk + (k >> 6)) * GA + (r & 127) * 68 + (k & 63);
        *(float4*)&dst[d] = v;
    }
}
// pack transpose of Wproj [O][H] as B operand rows n (N=1024, K=512)
__global__ void k_pack_T(const float* __restrict__ Wproj, float* __restrict__ dst) {
    int i = blockIdx.x * blockDim.x + threadIdx.x;
    if (i < HH * OO) {
        int n = i >> 9, o = i & 511;
        float v = tf32t(Wproj[(size_t)o * HH + n]);
        size_t d = ((size_t)(n >> 7) * 8 + (o >> 6)) * GA + (n & 127) * 68 + (o & 63);
        dst[d] = v;
    }
}
// pack W [4H][H] fp32 -> fp16 rec image [nt64][ch8][row64][136]
__global__ void k_pack_w16(const float* __restrict__ W, __half* __restrict__ dst) {
    int i = blockIdx.x * blockDim.x + threadIdx.x;   // 64*8*64*128 = 4194304
    if (i < 64 * 8 * 64 * 128) {
        int kl = i & 127, r = (i >> 7) & 63, ch = (i >> 13) & 7, nt = i >> 16;
        int gr = (r >> 4) * 1024 + nt * 16 + (r & 15);
        dst[(((size_t)nt * 8 + ch) * 64 + r) * 136 + kl] =
            __float2half(W[(size_t)gr * HH + ch * 128 + kl]);
    }
}

// ---------------- bulk-fed tf32 GEMM on packed operands ----------------
// mode 1: P store (+bias). mode 2: final out remap (+bias). mode 3: Weff -> fp16 image (+addm).
__global__ void __launch_bounds__(256) k_gemmB(
        const float* __restrict__ Apk, const float* __restrict__ Bpk,
        float* __restrict__ C, int ldc, int K,
        const float* __restrict__ bias, const float* __restrict__ addm, int mode) {
    extern __shared__ float sm[];
    unsigned sbase = (unsigned)__cvta_generic_to_shared(sm);
    unsigned barb  = sbase + 4 * GA * 4;
    const int tid = threadIdx.x;
    const int m0 = blockIdx.y * 128, n0 = blockIdx.x * 128;
    const int w = tid >> 5, wm = w >> 1, wn = w & 1;
    const int nKc = K >> 6;

    if (tid < 2) mbar_init(barb + tid * 8, 1);
    __syncthreads();

    auto issue = [&](int i) {
        if (tid == 0) {
            int st = i & 1;
            mbar_expect(barb + st * 8, 2 * GA * 4);
            bulk_g2s(sbase + (unsigned)(st * GA) * 4,
                     Apk + ((size_t)blockIdx.y * nKc + i) * GA, GA * 4, barb + st * 8);
            bulk_g2s(sbase + (unsigned)((2 + st) * GA) * 4,
                     Bpk + ((size_t)blockIdx.x * nKc + i) * GA, GA * 4, barb + st * 8);
        }
    };

    wmma::fragment<wmma::accumulator, 16, 16, 8, float> acc[2][4];
    #pragma unroll
    for (int i = 0; i < 2; i++)
        #pragma unroll
        for (int j = 0; j < 4; j++) wmma::fill_fragment(acc[i][j], 0.f);

    issue(0);
    if (nKc > 1) issue(1);

    for (int it = 0; it < nKc; it++) {
        int st = it & 1;
        mbar_wait(barb + st * 8, (it >> 1) & 1);
        const float* a = sm + st * GA;
        const float* b = sm + (2 + st) * GA;
        #pragma unroll
        for (int kk = 0; kk < 8; kk++) {
            wmma::fragment<wmma::matrix_a, 16, 16, 8, wmma::precision::tf32, wmma::row_major> a0, a1;
            wmma::fragment<wmma::matrix_b, 16, 16, 8, wmma::precision::tf32, wmma::col_major> bf[4];
            wmma::load_matrix_sync(a0, &a[(wm * 32) * 68 + kk * 8], 68);
            wmma::load_matrix_sync(a1, &a[(wm * 32 + 16) * 68 + kk * 8], 68);
            #pragma unroll
            for (int t = 0; t < 4; t++)
                wmma::load_matrix_sync(bf[t], &b[(wn * 64 + t * 16) * 68 + kk * 8], 68);
            #pragma unroll
            for (int t = 0; t < 4; t++) {
                wmma::mma_sync(acc[0][t], a0, bf[t], acc[0][t]);
                wmma::mma_sync(acc[1][t], a1, bf[t], acc[1][t]);
            }
        }
        __syncthreads();
        if (it + 2 < nKc) issue(it + 2);
    }

    float* sC = sm;
    #pragma unroll
    for (int i = 0; i < 2; i++)
        #pragma unroll
        for (int t = 0; t < 4; t++)
            wmma::store_matrix_sync(&sC[(wm * 32 + i * 16) * 132 + wn * 64 + t * 16],
                                    acc[i][t], 132, wmma::mem_row_major);
    __syncthreads();

    for (int idx = tid; idx < 128 * 128; idx += 256) {
        int m = idx >> 7, n = idx & 127;
        float v = sC[m * 132 + n];
        if (bias) v += bias[n0 + n];
        if (mode == 1) {            // P: GEMM row r = b*256+s -> Ppk[s][cta][col][m]
            int r = m0 + m, ng = n0 + n;
            int bb = r >> 8, s = r & 255;
            int g = ng >> 10, cc = ng & 1023, nt2 = cc >> 4, j = cc & 15;
            int cta = 2 * nt2 + (bb >> 6);
            C[((size_t)s * 128 + cta) * 4096 + (g * 16 + j) * 64 + (bb & 63)] = v;
        } else if (mode == 2) {     // final: r = t*128+b -> out[b][t][n]
            int r = m0 + m; int b = r & 127, t = r >> 7;
            C[((size_t)b * TT + t) * OO + n0 + n] = v;
        } else {                    // mode 3: Weff -> fp16 rec image (+Whh_d)
            int gr = m0 + m, k = n0 + n;
            v += addm[(size_t)gr * ldc + k];
            int g = gr >> 10, cc = gr & 1023, nt2 = cc >> 4, r = g * 16 + (cc & 15);
            ((__half*)C)[(((size_t)nt2 * 8 + (k >> 7)) * 64 + r) * 136 + (k & 127)] =
                __float2half(v);
        }
    }
}

// ---------------- persistent fp16 recurrence ----------------
// smem bytes: A 2x18432 @0 | Wres 8x17408 @36864 | sC0 @176128 | sC1 @193536 | bars @210944
#define RS_W    36864u
#define RS_C0   176128u
#define RS_C1   193536u
#define RS_BAR  210944u
#define RS_SMEM 210960

__global__ void __launch_bounds__(256, 1) k_rec16(
        const float* __restrict__ Ppk,
        const __half* __restrict__ WtE,
        const __half* __restrict__ WtD,
        const __half* __restrict__ WtF,
        const float* __restrict__ bdec,
        const float* __restrict__ beff,
        __half* __restrict__ hT16,
        float* __restrict__ Hallpk) {
    extern __shared__ __align__(128) char smc[];
    __half* sA = (__half*)smc;
    __half* sW = (__half*)(smc + RS_W);
    float* sC0 = (float*)(smc + RS_C0);
    float* sC1 = (float*)(smc + RS_C1);
    unsigned sb   = (unsigned)__cvta_generic_to_shared(smc);
    unsigned barb = sb + RS_BAR;

    const int tid = threadIdx.x, cta = blockIdx.x;
    const int mt = cta & 1, nt = cta >> 1, nb = nt * 16;
    const int w = tid >> 5;
    const int wm = w & 1, wn = (w >> 1) & 1, wk = w >> 2;
    const int mloc = tid & 63, j0 = tid >> 6;

    if (tid < 2) mbar_init(barb + tid * 8, 1);
    __syncthreads();

    float cst[4];
    #pragma unroll
    for (int jj = 0; jj < 4; jj++) cst[jj] = 0.f;

    int epoch = 0;

    for (int s = 0; s < NSTEP; s++) {
        const bool wload = (s == 0) || (s == SS) || (s == SS + 1);
        const __half* Wsrc = ((s < SS) ? WtE : ((s == SS) ? WtD : WtF))
                             + (size_t)nt * 69632;               // 8*8704
        const __half* Asrc = hT16 + (size_t)((s & 1) * 2 + mt) * 73728;   // 8*9216
        __half* Adst = hT16 + (size_t)(((s + 1) & 1) * 2 + mt) * 73728;

        auto issue = [&](int c) {
            int st = c & 1;
            unsigned tx = 18432u + (wload ? 17408u : 0u);
            mbar_expect(barb + st * 8, tx);
            bulk_g2s(sb + (unsigned)(st * 18432), Asrc + (size_t)c * 9216,
                     18432, barb + st * 8);
            if (wload)
                bulk_g2s(sb + RS_W + (unsigned)c * 17408, Wsrc + (size_t)c * 8704,
                         17408, barb + st * 8);
        };

        if (tid == 0) { issue(0); issue(1); }

        // prefetch P / bias into registers (hidden behind the MMA loop)
        float pv[16];
        if (s < SS) {
            const float* Ps = Ppk + ((size_t)s * 128 + cta) * 4096;
            #pragma unroll
            for (int g = 0; g < 4; g++)
                #pragma unroll
                for (int jj = 0; jj < 4; jj++)
                    pv[g * 4 + jj] = Ps[(g * 16 + j0 + 4 * jj) * 64 + mloc];
        } else {
            const float* gb = (s == SS) ? bdec : beff;
            #pragma unroll
            for (int g = 0; g < 4; g++)
                #pragma unroll
                for (int jj = 0; jj < 4; jj++)
                    pv[g * 4 + jj] = gb[g * 1024 + nb + j0 + 4 * jj];
        }

        wmma::fragment<wmma::accumulator, 16, 16, 16, float> acc[2][2];
        #pragma unroll
        for (int i = 0; i < 2; i++)
            #pragma unroll
            for (int q = 0; q < 2; q++) wmma::fill_fragment(acc[i][q], 0.f);

        for (int c = 0; c < 8; c++) {
            int st = c & 1;
            mbar_wait(barb + st * 8, (c >> 1) & 1);
            const __half* A = sA + st * 9216;       // [k128][72m]
            const __half* Wc = sW + (size_t)c * 8704;   // [64r][136k]
            #pragma unroll
            for (int kk = 0; kk < 4; kk++) {
                int k0 = wk * 64 + kk * 16;
                wmma::fragment<wmma::matrix_a, 16, 16, 16, __half, wmma::col_major> a0, a1;
                wmma::fragment<wmma::matrix_b, 16, 16, 16, __half, wmma::col_major> b0, b1;
                wmma::load_matrix_sync(a0, &A[(size_t)k0 * 72 + wm * 32], 72);
                wmma::load_matrix_sync(a1, &A[(size_t)k0 * 72 + wm * 32 + 16], 72);
                wmma::load_matrix_sync(b0, &Wc[(size_t)(wn * 32) * 136 + k0], 136);
                wmma::load_matrix_sync(b1, &Wc[(size_t)(wn * 32 + 16) * 136 + k0], 136);
                wmma::mma_sync(acc[0][0], a0, b0, acc[0][0]);
                wmma::mma_sync(acc[0][1], a0, b1, acc[0][1]);
                wmma::mma_sync(acc[1][0], a1, b0, acc[1][0]);
                wmma::mma_sync(acc[1][1], a1, b1, acc[1][1]);
            }
            __syncthreads();
            if (tid == 0 && c + 2 < 8) issue(c + 2);
        }

        float* sCd = (wk == 0) ? sC0 : sC1;
        #pragma unroll
        for (int i = 0; i < 2; i++)
            #pragma unroll
            for (int q = 0; q < 2; q++)
                wmma::store_matrix_sync(&sCd[(wm * 32 + i * 16) * 68 + wn * 32 + q * 16],
                                        acc[i][q], 68, wmma::mem_row_major);
        __syncthreads();

        // pointwise (registers; m-minor thread map)
        #pragma unroll
        for (int jj = 0; jj < 4; jj++) {
            int j = j0 + 4 * jj;
            int n = nb + j;
            float Gi = sC0[mloc * 68 + j]      + sC1[mloc * 68 + j]      + pv[jj];
            float Gf = sC0[mloc * 68 + 16 + j] + sC1[mloc * 68 + 16 + j] + pv[4 + jj];
            float Gg = sC0[mloc * 68 + 32 + j] + sC1[mloc * 68 + 32 + j] + pv[8 + jj];
            float Go = sC0[mloc * 68 + 48 + j] + sC1[mloc * 68 + 48 + j] + pv[12 + jj];
            float si = 1.f / (1.f + __expf(-Gi));
            float sf = 1.f / (1.f + __expf(-Gf));
            float so = 1.f / (1.f + __expf(-Go));
            float tg = __fdividef(2.f, 1.f + __expf(-2.f * Gg)) - 1.f;
            float cn = sf * cst[jj] + si * tg;
            cst[jj] = cn;
            float tc = __fdividef(2.f, 1.f + __expf(-2.f * cn)) - 1.f;
            float hn = so * tc;
            Adst[((size_t)(n >> 7) * 128 + (n & 127)) * 72 + mloc] = __float2half(hn);
            if (s >= SS) {
                int t = s - SS;
                Hallpk[(((size_t)t * 16 + (n >> 6)) * 128 + mt * 64 + mloc) * 68 + (n & 63)]
                    = tf32t(hn);
            }
        }

        if (s < NSTEP - 1) gridbar2(mt, epoch);
    }
}

// ---------------- host launch ----------------
extern "C" void kernel_launch(void* const* d_in, const int* in_sizes, int n_in,
                              void* d_out, int out_size) {
    int wbase = (n_in >= 12 && in_sizes[1] == 1) ? 2 : 1;

    const float* x     = (const float*)d_in[0];
    const float* Wih_e = (const float*)d_in[wbase + 0];
    const float* Whh_e = (const float*)d_in[wbase + 1];
    const float* bih_e = (const float*)d_in[wbase + 2];
    const float* bhh_e = (const float*)d_in[wbase + 3];
    const float* Wih_d = (const float*)d_in[wbase + 4];
    const float* Whh_d = (const float*)d_in[wbase + 5];
    const float* bih_d = (const float*)d_in[wbase + 6];
    const float* bhh_d = (const float*)d_in[wbase + 7];
    const float* Wproj = (const float*)d_in[wbase + 8];
    const float* bproj = (const float*)d_in[wbase + 9];
    float* out = (float*)d_out;

    float *Ppk, *xpk, *WihEpk, *WihDpk, *WpTpk, *Wprojpk, *Hallpk;
    float *benc, *bdec, *beff;
    __half *WtE, *WtD, *WtF, *hT16;
    cudaGetSymbolAddress((void**)&Ppk,     g_Ppk);
    cudaGetSymbolAddress((void**)&xpk,     g_xpk);
    cudaGetSymbolAddress((void**)&WihEpk,  g_WihEpk);
    cudaGetSymbolAddress((void**)&WihDpk,  g_WihDpk);
    cudaGetSymbolAddress((void**)&WpTpk,   g_WpTpk);
    cudaGetSymbolAddress((void**)&Wprojpk, g_Wprojpk);
    cudaGetSymbolAddress((void**)&Hallpk,  g_Hallpk);
    cudaGetSymbolAddress((void**)&WtE,     g_Wt16E);
    cudaGetSymbolAddress((void**)&WtD,     g_Wt16D);
    cudaGetSymbolAddress((void**)&WtF,     g_Wt16F);
    cudaGetSymbolAddress((void**)&hT16,    g_hT16);
    cudaGetSymbolAddress((void**)&benc,    g_benc);
    cudaGetSymbolAddress((void**)&bdec,    g_bdec);
    cudaGetSymbolAddress((void**)&beff,    g_beff);

    const int gemmSmem = 4 * GA * 4 + 64;
    cudaFuncSetAttribute(k_gemmB, cudaFuncAttributeMaxDynamicSharedMemorySize, gemmSmem);
    cudaFuncSetAttribute(k_rec16, cudaFuncAttributeMaxDynamicSharedMemorySize, RS_SMEM);

    // biases
    k_vec_add<<<16, 256>>>(bih_e, bhh_e, benc, G4H);
    k_vec_add<<<16, 256>>>(bih_d, bhh_d, bdec, G4H);
    k_beff<<<16, 256>>>(Wih_d, bproj, bdec, beff);

    // packs
    k_pack<<<(int)(((size_t)BB * SS * II / 4 + 255) / 256), 256>>>(
        x, xpk, II, (size_t)BB * SS * II);
    k_pack<<<(int)(((size_t)G4H * II / 4 + 255) / 256), 256>>>(
        Wih_e, WihEpk, II, (size_t)G4H * II);
    k_pack<<<(int)(((size_t)G4H * OO / 4 + 255) / 256), 256>>>(
        Wih_d, WihDpk, OO, (size_t)G4H * OO);
    k_pack<<<(int)(((size_t)OO * HH / 4 + 255) / 256), 256>>>(
        Wproj, Wprojpk, HH, (size_t)OO * HH);
    k_pack_T<<<(HH * OO + 255) / 256, 256>>>(Wproj, WpTpk);
    k_pack_w16<<<(64 * 8 * 64 * 128) / 256, 256>>>(Whh_e, WtE);
    k_pack_w16<<<(64 * 8 * 64 * 128) / 256, 256>>>(Whh_d, WtD);

    // W_eff = W_ih_dec @ W_proj + W_hh_dec -> fp16 rec image (mode 3)
    k_gemmB<<<dim3(HH / 128, G4H / 128), 256, gemmSmem>>>(
        WihDpk, WpTpk, (float*)WtF, HH, OO, nullptr, Whh_d, 3);

    // P = X @ W_ih_enc^T + b_enc -> Ppk (mode 1)
    k_gemmB<<<dim3(G4H / 128, (BB * SS) / 128), 256, gemmSmem>>>(
        xpk, WihEpk, Ppk, 0, II, benc, nullptr, 1);

    // zero h images (both buffers), reset barriers, run the recurrence
    k_zero<<<(2 * 2 * 8 * 128 * 72 / 2 + 255) / 256, 256>>>((float*)hT16,
                                                            2 * 2 * 8 * 128 * 72 / 2);
    k_reset_bar<<<1, 1>>>();
    k_rec16<<<NCTA_REC, 256, RS_SMEM>>>(Ppk, WtE, WtD, WtF, bdec, beff, hT16, Hallpk);

    // Y = Hall @ W_proj^T + b_proj -> out[b][t][o] (mode 2)
    k_gemmB<<<dim3(OO / 128, (BB * TT) / 128), 256, gemmSmem>>>(
        Hallpk, Wprojpk, out, 0, HH, bproj, nullptr, 2);
}